// round 8
// baseline (speedup 1.0000x reference)
#include <cuda_runtime.h>
#include <cuda_bf16.h>
#include <stdint.h>
#include <math.h>

#define Bb   4
#define Nn   4096
#define Dd   512
#define Hh   8
#define DHd  64
#define Mm   266
#define BHh  32
#define BNn  16384
#define K2   1536      // big-GEMM split K (hi|lo|hi)
#define PK   192       // phi split K
#define PN   320       // td column stride
#define MX   288       // padded feature count (m)
#define NROWS ((size_t)BHh * Nn)

// -------------------- scratch --------------------
__device__ float g_q  [NROWS * DHd];
__device__ float g_k  [NROWS * DHd];
__device__ float g_v  [NROWS * DHd];
__device__ float g_ctx [(size_t)BHh * MX * DHd];
__device__ float g_ksum[BHh * Mm];
__device__ float g_kmax[BHh];
__device__ float g_diagq[NROWS];
__device__ float g_diagk[NROWS];
__device__ float g_dinv[NROWS];
__device__ float g_tdq[NROWS * PN];
__device__ float g_tdk[NROWS * PN];
__device__ __nv_bfloat16 g_qx[NROWS * PK];
__device__ __nv_bfloat16 g_kx[NROWS * PK];
__device__ __nv_bfloat16 g_projB[384 * PK];

// feature planes (split bf16)
__device__ __nv_bfloat16 g_kph[(size_t)BHh * MX * Nn];   // [bh][m][n]
__device__ __nv_bfloat16 g_kpl[(size_t)BHh * MX * Nn];
__device__ __nv_bfloat16 g_qph[NROWS * MX];              // [bh][n][m]
__device__ __nv_bfloat16 g_qpl[NROWS * MX];
__device__ __nv_bfloat16 g_vth[(size_t)BHh * DHd * Nn];  // [bh][dh][n]
__device__ __nv_bfloat16 g_vtl[(size_t)BHh * DHd * Nn];
__device__ __nv_bfloat16 g_cth[(size_t)BHh * DHd * MX];  // [bh][dh][m]
__device__ __nv_bfloat16 g_ctl[(size_t)BHh * DHd * MX];

__device__ __nv_bfloat16 g_x2   [(size_t)BNn * K2];
__device__ __nv_bfloat16 g_attn2[(size_t)BNn * K2];
__device__ __nv_bfloat16 g_wq2  [(size_t)Dd * K2];
__device__ __nv_bfloat16 g_wk2  [(size_t)Dd * K2];
__device__ __nv_bfloat16 g_wv2  [(size_t)Dd * K2];
__device__ __nv_bfloat16 g_wo2  [(size_t)Dd * K2];

// -------------------- helpers --------------------
__device__ __forceinline__ uint32_t smem_to_u32(const void* p) {
    uint32_t a;
    asm("{ .reg .u64 t; cvta.to.shared.u64 t, %1; cvt.u32.u64 %0, t; }"
        : "=r"(a) : "l"(p));
    return a;
}

#define CP_ASYNC16(dst, src) \
    asm volatile("cp.async.cg.shared.global [%0], [%1], 16;" \
                 :: "r"(dst), "l"(src) : "memory")
#define CP_COMMIT()  asm volatile("cp.async.commit_group;" ::: "memory")
#define CP_WAIT1()   asm volatile("cp.async.wait_group 1;" ::: "memory")
#define CP_WAIT0()   asm volatile("cp.async.wait_group 0;" ::: "memory")

__device__ __forceinline__ void ldm_x4(uint32_t& r0, uint32_t& r1,
                                       uint32_t& r2, uint32_t& r3, uint32_t addr) {
    asm volatile("ldmatrix.sync.aligned.m8n8.x4.shared.b16 {%0,%1,%2,%3}, [%4];"
                 : "=r"(r0), "=r"(r1), "=r"(r2), "=r"(r3) : "r"(addr));
}

__device__ __forceinline__ void mma16816(float* c, const uint32_t* a, const uint32_t* b) {
    asm volatile(
        "mma.sync.aligned.m16n8k16.row.col.f32.bf16.bf16.f32 "
        "{%0,%1,%2,%3}, {%4,%5,%6,%7}, {%8,%9}, {%0,%1,%2,%3};"
        : "+f"(c[0]), "+f"(c[1]), "+f"(c[2]), "+f"(c[3])
        : "r"(a[0]), "r"(a[1]), "r"(a[2]), "r"(a[3]), "r"(b[0]), "r"(b[1]));
}

__device__ __forceinline__ void atomicMaxF(float* addr, float val) {
    int* ai = (int*)addr;
    int old = *ai;
    while (__int_as_float(old) < val) {
        int assumed = old;
        old = atomicCAS(ai, assumed, __float_as_int(val));
        if (old == assumed) break;
    }
}

__device__ __forceinline__ float fast_exp(float x) {
    float y = fmaxf(x * 1.4426950408889634f, -126.0f);
    float r = rintf(y);
    float f = y - r;
    float p = 1.5403530e-4f;
    p = fmaf(p, f, 1.3333558e-3f);
    p = fmaf(p, f, 9.6181291e-3f);
    p = fmaf(p, f, 5.5504109e-2f);
    p = fmaf(p, f, 2.4022651e-1f);
    p = fmaf(p, f, 6.9314718e-1f);
    p = fmaf(p, f, 1.0f);
    int e = (int)r;
    float s = __int_as_float((e + 127) << 23);
    return p * s;
}

__device__ __forceinline__ uint32_t packbf(float a, float b) {
    __nv_bfloat162 t;
    t.x = __float2bfloat16(a);
    t.y = __float2bfloat16(b);
    return *(uint32_t*)&t;
}

__device__ __forceinline__ void split2(float v, __nv_bfloat16& h, __nv_bfloat16& l) {
    h = __float2bfloat16(v);
    l = __float2bfloat16(v - __bfloat162float(h));
}

#define NORMALIZER 0.35355339059327373f
#define RATIO      0.061313934f
#define EPSF       1e-4f

// -------------------- init --------------------
__global__ void k_init() {
    int i = blockIdx.x * 256 + threadIdx.x;
    if (i < BHh * MX * DHd) g_ctx[i]  = 0.0f;
    if (i < BHh * Mm)       g_ksum[i] = 0.0f;
    if (i < BHh)            g_kmax[i] = -3.0e38f;
}

// -------------------- fp32 -> split bf16 for big GEMMs --------------------
__global__ __launch_bounds__(256) void k_split(const float* __restrict__ src,
                                               __nv_bfloat16* __restrict__ dst,
                                               int nrows, int loOff, int dupOff) {
    int i = blockIdx.x * 256 + threadIdx.x;
    if (i >= nrows * 128) return;
    int r = i >> 7;
    int c = (i & 127) << 2;
    float4 v = *(const float4*)(src + (size_t)r * 512 + c);
    __nv_bfloat16 h0, l0, h1, l1, h2, l2, h3, l3;
    split2(v.x, h0, l0); split2(v.y, h1, l1);
    split2(v.z, h2, l2); split2(v.w, h3, l3);
    size_t rb = (size_t)r * K2;
    __nv_bfloat162 H01; H01.x = h0; H01.y = h1;
    __nv_bfloat162 H23; H23.x = h2; H23.y = h3;
    __nv_bfloat162 L01; L01.x = l0; L01.y = l1;
    __nv_bfloat162 L23; L23.x = l2; L23.y = l3;
    *(__nv_bfloat162*)(dst + rb + c)              = H01;
    *(__nv_bfloat162*)(dst + rb + c + 2)          = H23;
    *(__nv_bfloat162*)(dst + rb + loOff + c)      = L01;
    *(__nv_bfloat162*)(dst + rb + loOff + c + 2)  = L23;
    *(__nv_bfloat162*)(dst + rb + dupOff + c)     = H01;
    *(__nv_bfloat162*)(dst + rb + dupOff + c + 2) = H23;
}

// -------------------- projB --------------------
__global__ __launch_bounds__(256) void k_projB(const float* __restrict__ proj) {
    int i = blockIdx.x * 256 + threadIdx.x;
    if (i >= 384 * 64) return;
    int m = i >> 6, c = i & 63;
    float v = (m < Mm) ? proj[m * 64 + c] : 0.f;
    __nv_bfloat16 h, l;
    split2(v, h, l);
    g_projB[m * PK + c]        = h;
    g_projB[m * PK + 64 + c]   = h;
    g_projB[m * PK + 128 + c]  = l;
}

// -------------------- prep: q/k -> scaled split rows [hi|lo|hi], diag -------------
__global__ __launch_bounds__(256) void k_prep(int sel) {
    const float* src = sel ? g_k : g_q;
    __nv_bfloat16* dst = sel ? g_kx : g_qx;
    float* diag = sel ? g_diagk : g_diagq;
    int gid = blockIdx.x * 256 + threadIdx.x;
    int row = gid >> 3, sub = gid & 7;
    const float* s = src + (size_t)row * 64 + sub * 8;
    float4 a = *(const float4*)s;
    float4 b = *(const float4*)(s + 4);
    a.x *= NORMALIZER; a.y *= NORMALIZER; a.z *= NORMALIZER; a.w *= NORMALIZER;
    b.x *= NORMALIZER; b.y *= NORMALIZER; b.z *= NORMALIZER; b.w *= NORMALIZER;
    float ss = a.x * a.x + a.y * a.y + a.z * a.z + a.w * a.w
             + b.x * b.x + b.y * b.y + b.z * b.z + b.w * b.w;
    ss += __shfl_xor_sync(0xffffffffu, ss, 1);
    ss += __shfl_xor_sync(0xffffffffu, ss, 2);
    ss += __shfl_xor_sync(0xffffffffu, ss, 4);
    if (sub == 0) diag[row] = 0.5f * ss;
    uint4 H, L;
    H.x = packbf(a.x, a.y); H.y = packbf(a.z, a.w);
    H.z = packbf(b.x, b.y); H.w = packbf(b.z, b.w);
    __nv_bfloat162 h0 = *(__nv_bfloat162*)&H.x;
    __nv_bfloat162 h1 = *(__nv_bfloat162*)&H.y;
    __nv_bfloat162 h2 = *(__nv_bfloat162*)&H.z;
    __nv_bfloat162 h3 = *(__nv_bfloat162*)&H.w;
    L.x = packbf(a.x - __bfloat162float(h0.x), a.y - __bfloat162float(h0.y));
    L.y = packbf(a.z - __bfloat162float(h1.x), a.w - __bfloat162float(h1.y));
    L.z = packbf(b.x - __bfloat162float(h2.x), b.y - __bfloat162float(h2.y));
    L.w = packbf(b.z - __bfloat162float(h3.x), b.w - __bfloat162float(h3.y));
    __nv_bfloat16* d = dst + (size_t)row * PK + sub * 8;
    *(uint4*)d          = H;
    *(uint4*)(d + 64)   = L;
    *(uint4*)(d + 128)  = H;
}

// -------------------- big GEMM (validated) --------------------
#define ASTR 40
#define TILE_B (128 * ASTR)

#define LOAD_TILE(buf, t) do {                                         \
    uint32_t _o = (uint32_t)(buf) * (TILE_B * 2);                      \
    const __nv_bfloat16* _a = Arow + (t) * 32;                         \
    const __nv_bfloat16* _b = Brow + (t) * 32;                         \
    CP_ASYNC16(sAdst + _o,      _a);                                   \
    CP_ASYNC16(sAdst + _o + 16, _a + 8);                               \
    CP_ASYNC16(sBdst + _o,      _b);                                   \
    CP_ASYNC16(sBdst + _o + 16, _b + 8);                               \
} while (0)

#define MMA_BODY(ab, bb) do {                                                            \
    for (int ks = 0; ks < 32; ks += 16) {                                                \
        uint32_t a[2][4];                                                                \
        for (int mt = 0; mt < 2; mt++) {                                                 \
            uint32_t addr = (ab) +                                                       \
                (uint32_t)((m0 + mt * 16 + (lane & 15)) * ASTR + ks + ((lane >> 4) << 3)) * 2; \
            ldm_x4(a[mt][0], a[mt][1], a[mt][2], a[mt][3], addr);                        \
        }                                                                                \
        uint32_t b[8][2];                                                                \
        for (int p = 0; p < 4; p++) {                                                    \
            uint32_t addr = (bb) +                                                       \
                (uint32_t)((n0 + p * 16 + (lane & 7) + ((lane >> 4) << 3)) * ASTR + ks + (lane & 8)) * 2; \
            ldm_x4(b[2 * p][0], b[2 * p][1], b[2 * p + 1][0], b[2 * p + 1][1], addr);    \
        }                                                                                \
        for (int mt = 0; mt < 2; mt++)                                                   \
            for (int nt = 0; nt < 8; nt++)                                               \
                mma16816(acc[mt][nt], a[mt], b[nt]);                                     \
    }                                                                                    \
} while (0)

__global__ __launch_bounds__(256) void k_gemm(const __nv_bfloat16* __restrict__ A,
                                              const __nv_bfloat16* __restrict__ Bw,
                                              float* __restrict__ C,
                                              const float* __restrict__ xres,
                                              const float* __restrict__ bo,
                                              int finalmode) {
    __shared__ __nv_bfloat16 sA[2][TILE_B];
    __shared__ __nv_bfloat16 sB[2][TILE_B];
    int tid = threadIdx.x, lane = tid & 31, w = tid >> 5;
    int m0 = (w & 3) * 32, n0 = (w >> 2) * 64;
    int r0 = blockIdx.x * 128, e0 = blockIdx.y * 128;
    uint32_t sAu = smem_to_u32(sA), sBu = smem_to_u32(sB);

    float acc[2][8][4];
#pragma unroll
    for (int i = 0; i < 2; i++)
#pragma unroll
        for (int j = 0; j < 8; j++)
#pragma unroll
            for (int l = 0; l < 4; l++) acc[i][j][l] = 0.f;

    int lrow = tid >> 1, lcol = (tid & 1) << 4;
    const __nv_bfloat16* Arow = A + (size_t)(r0 + lrow) * K2 + lcol;
    const __nv_bfloat16* Brow = Bw + (size_t)(e0 + lrow) * K2 + lcol;
    uint32_t sAdst = sAu + (uint32_t)(lrow * ASTR + lcol) * 2;
    uint32_t sBdst = sBu + (uint32_t)(lrow * ASTR + lcol) * 2;

    LOAD_TILE(0, 0);
    CP_COMMIT();
    const int NT = K2 / 32;
#pragma unroll 1
    for (int t = 0; t < NT; ++t) {
        int buf = t & 1;
        if (t + 1 < NT) { LOAD_TILE(buf ^ 1, t + 1); CP_COMMIT(); CP_WAIT1(); }
        else           { CP_WAIT0(); }
        __syncthreads();
        uint32_t ab = sAu + (uint32_t)buf * (TILE_B * 2);
        uint32_t bb = sBu + (uint32_t)buf * (TILE_B * 2);
        MMA_BODY(ab, bb);
        __syncthreads();
    }

    int gid = lane >> 2, tig = lane & 3;
#pragma unroll
    for (int mt = 0; mt < 2; mt++) {
#pragma unroll
        for (int nt = 0; nt < 8; nt++) {
            int r = r0 + m0 + mt * 16 + gid;
            int e = e0 + n0 + nt * 8 + tig * 2;
            float2 v01 = make_float2(acc[mt][nt][0], acc[mt][nt][1]);
            float2 v23 = make_float2(acc[mt][nt][2], acc[mt][nt][3]);
            if (!finalmode) {
                int b = r >> 12, n = r & 4095;
                int h = e >> 6, dh = e & 63;
                float* d0 = C + (((size_t)((b << 3) + h) * Nn + n) * DHd + dh);
                *(float2*)d0 = v01;
                *(float2*)(d0 + 8 * DHd) = v23;
            } else {
                size_t b0 = (size_t)r * Dd + e;
                float2 x0 = *(const float2*)(xres + b0);
                float2 x1 = *(const float2*)(xres + b0 + 8 * Dd);
                float2 bv = *(const float2*)(bo + e);
                *(float2*)(C + b0) = make_float2(x0.x + bv.x + v01.x, x0.y + bv.y + v01.y);
                *(float2*)(C + b0 + 8 * Dd) = make_float2(x1.x + bv.x + v23.x, x1.y + bv.y + v23.y);
            }
        }
    }
}

// -------------------- phi GEMM: td = X @ projB^T (+ per-head max for k) ----------
__global__ __launch_bounds__(256) void k_phi(int sel) {
    __shared__ __nv_bfloat16 sA[2][TILE_B];
    __shared__ __nv_bfloat16 sB[2][TILE_B];
    __shared__ float smax;
    const __nv_bfloat16* A = sel ? g_kx : g_qx;
    float* td = sel ? g_tdk : g_tdq;
    int tid = threadIdx.x, lane = tid & 31, w = tid >> 5;
    int m0 = (w & 3) * 32, n0 = (w >> 2) * 64;
    int r0 = blockIdx.x * 128, e0 = blockIdx.y * 128;
    uint32_t sAu = smem_to_u32(sA), sBu = smem_to_u32(sB);
    if (tid == 0) smax = -3.0e38f;

    float acc[2][8][4];
#pragma unroll
    for (int i = 0; i < 2; i++)
#pragma unroll
        for (int j = 0; j < 8; j++)
#pragma unroll
            for (int l = 0; l < 4; l++) acc[i][j][l] = 0.f;

    int lrow = tid >> 1, lcol = (tid & 1) << 4;
    const __nv_bfloat16* Arow = A + (size_t)(r0 + lrow) * PK + lcol;
    const __nv_bfloat16* Brow = g_projB + (size_t)(e0 + lrow) * PK + lcol;
    uint32_t sAdst = sAu + (uint32_t)(lrow * ASTR + lcol) * 2;
    uint32_t sBdst = sBu + (uint32_t)(lrow * ASTR + lcol) * 2;

    LOAD_TILE(0, 0);
    CP_COMMIT();
    const int NT = PK / 32;
#pragma unroll 1
    for (int t = 0; t < NT; ++t) {
        int buf = t & 1;
        if (t + 1 < NT) { LOAD_TILE(buf ^ 1, t + 1); CP_COMMIT(); CP_WAIT1(); }
        else           { CP_WAIT0(); }
        __syncthreads();
        uint32_t ab = sAu + (uint32_t)buf * (TILE_B * 2);
        uint32_t bb = sBu + (uint32_t)buf * (TILE_B * 2);
        MMA_BODY(ab, bb);
        __syncthreads();
    }

    int gid = lane >> 2, tig = lane & 3;
    float mymax = -3.0e38f;
#pragma unroll
    for (int mt = 0; mt < 2; mt++) {
#pragma unroll
        for (int nt = 0; nt < 8; nt++) {
            int r = r0 + m0 + mt * 16 + gid;
            int e = e0 + n0 + nt * 8 + tig * 2;
            if (e < PN) {
                *(float2*)(td + (size_t)r * PN + e) =
                    make_float2(acc[mt][nt][0], acc[mt][nt][1]);
                *(float2*)(td + (size_t)(r + 8) * PN + e) =
                    make_float2(acc[mt][nt][2], acc[mt][nt][3]);
            }
            if (e < Mm) {
                mymax = fmaxf(mymax, fmaxf(fmaxf(acc[mt][nt][0], acc[mt][nt][1]),
                                           fmaxf(acc[mt][nt][2], acc[mt][nt][3])));
            }
        }
    }
    if (sel) {
        atomicMaxF(&smax, mymax);
        __syncthreads();
        if (tid == 0) atomicMaxF(&g_kmax[blockIdx.x >> 5], smax);
    }
}

// -------------------- exp_k: kpT planes [bh][m][n] bf16, ksum ---------------------
__global__ __launch_bounds__(256) void k_exp_k() {
    __shared__ float diag_s[64];
    int tid = threadIdx.x, n0 = blockIdx.x * 64, bh = blockIdx.y;
    size_t gr0 = (size_t)bh * Nn + n0;
    if (tid < 64) diag_s[tid] = g_diagk[gr0 + tid];
    __syncthreads();
    float mx = g_kmax[bh];
    for (int m = tid; m < MX; m += 256) {
        size_t ob = ((size_t)bh * MX + m) * Nn + n0;
        if (m < Mm) {
            float cs = 0.f;
#pragma unroll 4
            for (int r = 0; r < 64; r++) {
                float t = g_tdk[(gr0 + r) * PN + m];
                float v = RATIO * (fast_exp(t - diag_s[r] - mx) + EPSF);
                __nv_bfloat16 h, l;
                split2(v, h, l);
                g_kph[ob + r] = h;
                g_kpl[ob + r] = l;
                cs += v;
            }
            atomicAdd(&g_ksum[bh * Mm + m], cs);
        } else {
            __nv_bfloat16 z = __float2bfloat16(0.f);
#pragma unroll 8
            for (int r = 0; r < 64; r++) { g_kph[ob + r] = z; g_kpl[ob + r] = z; }
        }
    }
}

// -------------------- exp_q: rowmax, qp planes [bh][n][m], dinv -------------------
__global__ __launch_bounds__(256) void k_exp_q() {
    __shared__ float ksum_s[Mm];
    int tid = threadIdx.x, n0 = blockIdx.x * 64, bh = blockIdx.y;
    size_t gr0 = (size_t)bh * Nn + n0;
    for (int i = tid; i < Mm; i += 256) ksum_s[i] = g_ksum[bh * Mm + i];
    __syncthreads();
    int row = tid >> 2, l4 = tid & 3;
    size_t gr = gr0 + row;
    const float* tdr = g_tdq + gr * PN;
    float pm = -3.0e38f;
    for (int m = l4; m < Mm; m += 4) pm = fmaxf(pm, tdr[m]);
    pm = fmaxf(pm, __shfl_xor_sync(0xffffffffu, pm, 1));
    pm = fmaxf(pm, __shfl_xor_sync(0xffffffffu, pm, 2));
    float dg = g_diagq[gr];
    float sum = 0.f;
    for (int m = l4; m < MX; m += 4) {
        float v = 0.f;
        if (m < Mm) {
            v = RATIO * (fast_exp(tdr[m] - dg - pm) + EPSF);
            sum += v * ksum_s[m];
        }
        __nv_bfloat16 h, l;
        split2(v, h, l);
        g_qph[gr * MX + m] = h;
        g_qpl[gr * MX + m] = l;
    }
    sum += __shfl_xor_sync(0xffffffffu, sum, 1);
    sum += __shfl_xor_sync(0xffffffffu, sum, 2);
    if (l4 == 0) g_dinv[gr] = 1.0f / sum;
}

// -------------------- v transpose + split: vT planes [bh][dh][n] ------------------
__global__ __launch_bounds__(256) void k_vt() {
    __shared__ float s[64][65];
    int n0 = blockIdx.x * 64, bh = blockIdx.y, tid = threadIdx.x;
    for (int i = tid; i < 64 * 64; i += 256) {
        int r = i >> 6, dh = i & 63;
        s[r][dh] = g_v[((size_t)bh * Nn + n0 + r) * DHd + dh];
    }
    __syncthreads();
    for (int i = tid; i < 64 * 64; i += 256) {
        int dh = i >> 6, j = i & 63;
        float v = s[j][dh];
        __nv_bfloat16 h, l;
        split2(v, h, l);
        size_t o = ((size_t)bh * DHd + dh) * Nn + n0 + j;
        g_vth[o] = h;
        g_vtl[o] = l;
    }
}

// -------------------- ctx transpose + split: ctxT planes [bh][dh][m] --------------
__global__ __launch_bounds__(256) void k_ctxT() {
    int bh = blockIdx.x, tid = threadIdx.x;
    for (int i = tid; i < DHd * MX; i += 256) {
        int dh = i / MX, m = i % MX;
        float v = g_ctx[((size_t)bh * MX + m) * DHd + dh];
        __nv_bfloat16 h, l;
        split2(v, h, l);
        size_t o = ((size_t)bh * DHd + dh) * MX + m;
        g_cth[o] = h;
        g_ctl[o] = l;
    }
}

// ==================== split-3 MMA tail kernels ====================
// acc += Ah*Bh + Al*Bh + Ah*Bl
#define MMA3_STEP(aHb, aLb, bHb, bLb, m0w) do {                                          \
    for (int ks = 0; ks < 32; ks += 16) {                                                \
        uint32_t ah[4], al[4];                                                           \
        uint32_t aoff = (uint32_t)((m0w + (lane & 15)) * ASTR + ks + ((lane >> 4) << 3)) * 2; \
        ldm_x4(ah[0], ah[1], ah[2], ah[3], (aHb) + aoff);                                \
        ldm_x4(al[0], al[1], al[2], al[3], (aLb) + aoff);                                \
        uint32_t bh_[8][2], bl_[8][2];                                                   \
        for (int p = 0; p < 4; p++) {                                                    \
            uint32_t boff = (uint32_t)((p * 16 + (lane & 7) + ((lane >> 4) << 3)) * ASTR + ks + (lane & 8)) * 2; \
            ldm_x4(bh_[2 * p][0], bh_[2 * p][1], bh_[2 * p + 1][0], bh_[2 * p + 1][1], (bHb) + boff); \
            ldm_x4(bl_[2 * p][0], bl_[2 * p][1], bl_[2 * p + 1][0], bl_[2 * p + 1][1], (bLb) + boff); \
        }                                                                                \
        for (int nt = 0; nt < 8; nt++) {                                                 \
            mma16816(acc[nt], ah, bh_[nt]);                                              \
            mma16816(acc[nt], al, bh_[nt]);                                              \
            mma16816(acc[nt], ah, bl_[nt]);                                              \
        }                                                                                \
    }                                                                                    \
} while (0)

// ---- ctx: C[m,dh] += sum_n kp[n,m]*v[n,dh]; A=kpT planes, B=vT planes ----
// grid (3 m-tiles of 96, 8 ksplit, 32 bh), 192 threads (6 m-warps x 64 cols)
#define CTX_AROWS 96
#define CTX_SEGS  1280    // (96*2 + 64*2) rows * 4 segs
#define CTX_BUFE  (CTX_AROWS * ASTR * 2 + 64 * ASTR * 2)   // bf16 elems per buffer
__global__ __launch_bounds__(192) void k_ctx_t() {
    extern __shared__ __nv_bfloat16 dsm[];
    int tid = threadIdx.x, lane = tid & 31, w = tid >> 5;
    int m0 = blockIdx.x * CTX_AROWS;
    int nc = blockIdx.y * 512;
    int bh = blockIdx.z;
    uint32_t base = smem_to_u32(dsm);
    // buffer layout: Ah[96*40] Al[96*40] Bh[64*40] Bl[64*40]
    const uint32_t oAl = CTX_AROWS * ASTR * 2;          // bytes
    const uint32_t oBh = oAl * 2;
    const uint32_t oBl = oBh + 64 * ASTR * 2;
    const uint32_t bufB = (uint32_t)CTX_BUFE * 2;

    float acc[8][4];
#pragma unroll
    for (int j = 0; j < 8; j++)
#pragma unroll
        for (int l = 0; l < 4; l++) acc[j][l] = 0.f;

    const __nv_bfloat16* kph = g_kph + ((size_t)bh * MX + m0) * Nn;
    const __nv_bfloat16* kpl = g_kpl + ((size_t)bh * MX + m0) * Nn;
    const __nv_bfloat16* vth = g_vth + (size_t)bh * DHd * Nn;
    const __nv_bfloat16* vtl = g_vtl + (size_t)bh * DHd * Nn;

#define CTX_LOAD(buf, t) do {                                                  \
    int _n0 = nc + (t) * 32;                                                   \
    uint32_t _bb = base + (uint32_t)(buf) * bufB;                              \
    for (int _i = 0; _i < 7; _i++) {                                           \
        int s = tid + _i * 192;                                                \
        if (s < CTX_SEGS) {                                                    \
            int cseg = s & 3;                                                  \
            const __nv_bfloat16* src;                                          \
            uint32_t dst;                                                      \
            if (s < 768) {                                                     \
                int pl = s >= 384;                                             \
                int r = (s - pl * 384) >> 2;                                   \
                src = (pl ? kpl : kph) + (size_t)r * Nn + _n0 + cseg * 8;      \
                dst = _bb + pl * oAl + (uint32_t)(r * ASTR + cseg * 8) * 2;    \
            } else {                                                           \
                int sB = s - 768;                                              \
                int pl = sB >= 256;                                            \
                int r = (sB - pl * 256) >> 2;                                  \
                src = (pl ? vtl : vth) + (size_t)r * Nn + _n0 + cseg * 8;      \
                dst = _bb + (pl ? oBl : oBh) + (uint32_t)(r * ASTR + cseg * 8) * 2; \
            }                                                                  \
            CP_ASYNC16(dst, src);                                              \
        }                                                                      \
    }                                                                          \
} while (0)

    CTX_LOAD(0, 0);
    CP_COMMIT();
#pragma unroll 1
    for (int t = 0; t < 16; ++t) {
        int buf = t & 1;
        if (t + 1 < 16) { CTX_LOAD(buf ^ 1, t + 1); CP_COMMIT(); CP_WAIT1(); }
        else           { CP_WAIT0(); }
        __syncthreads();
        uint32_t bb = base + (uint32_t)buf * bufB;
        int m0w = w * 16;
        MMA3_STEP(bb, bb + oAl, bb + oBh, bb + oBl, m0w);
        __syncthreads();
    }

    int gid = lane >> 2, tig = lane & 3;
#pragma unroll
    for (int nt = 0; nt < 8; nt++) {
        int m = m0 + w * 16 + gid;
        int c = nt * 8 + tig * 2;
        float* d0 = g_ctx + ((size_t)bh * MX + m) * DHd + c;
        atomicAdd(d0,     acc[nt][0]);
        atomicAdd(d0 + 1, acc[nt][1]);
        float* d1 = d0 + 8 * DHd;
        atomicAdd(d1,     acc[nt][2]);
        atomicAdd(d1 + 1, acc[nt][3]);
    }
}

// ---- out: C[n,dh] = dinv[n] * sum_m qp[n,m]*ctx[m,dh]; A=qp planes, B=ctxT planes ----
// grid (32 n-tiles of 128, 32 bh), 256 threads (8 m-warps x 64 cols)
#define OUT_SEGS 1536    // (128*2 + 64*2) rows * 4 segs
#define OUT_BUFE (128 * ASTR * 2 + 64 * ASTR * 2)
__global__ __launch_bounds__(256) void k_out_t() {
    extern __shared__ __nv_bfloat16 dsm[];
    int tid = threadIdx.x, lane = tid & 31, w = tid >> 5;
    int n0 = blockIdx.x * 128;
    int bh = blockIdx.y;
    uint32_t base = smem_to_u32(dsm);
    const uint32_t oAl = 128 * ASTR * 2;
    const uint32_t oBh = oAl * 2;
    const uint32_t oBl = oBh + 64 * ASTR * 2;
    const uint32_t bufB = (uint32_t)OUT_BUFE * 2;

    float acc[8][4];
#pragma unroll
    for (int j = 0; j < 8; j++)
#pragma unroll
        for (int l = 0; l < 4; l++) acc[j][l] = 0.f;

    const __nv_bfloat16* qph = g_qph + ((size_t)bh * Nn + n0) * MX;
    const __nv_bfloat16* qpl = g_qpl + ((size_t)bh * Nn + n0) * MX;
    const __nv_bfloat16* cth = g_cth + (size_t)bh * DHd * MX;
    const __nv_bfloat16* ctl = g_ctl + (size_t)bh * DHd * MX;

#define OUT_LOAD(buf, t) do {                                                  \
    int _k0 = (t) * 32;                                                        \
    uint32_t _bb = base + (uint32_t)(buf) * bufB;                              \
    for (int _i = 0; _i < 6; _i++) {                                           \
        int s = tid + _i * 256;                                                \
        int cseg = s & 3;                                                      \
        const __nv_bfloat16* src;                                              \
        uint32_t dst;                                                          \
        if (s < 1024) {                                                        \
            int pl = s >= 512;                                                 \
            int r = (s - pl * 512) >> 2;                                       \
            src = (pl ? qpl : qph) + (size_t)r * MX + _k0 + cseg * 8;          \
            dst = _bb + pl * oAl + (uint32_t)(r * ASTR + cseg * 8) * 2;        \
        } else {                                                               \
            int sB = s - 1024;                                                 \
            int pl = sB >= 256;                                                \
            int r = (sB - pl * 256) >> 2;                                      \
            src = (pl ? ctl : cth) + (size_t)r * MX + _k0 + cseg * 8;          \
            dst = _bb + (pl ? oBl : oBh) + (uint32_t)(r * ASTR + cseg * 8) * 2; \
        }                                                                      \
        CP_ASYNC16(dst, src);                                                  \
    }                                                                          \
} while (0)

    OUT_LOAD(0, 0);
    CP_COMMIT();
    const int NT = MX / 32;   // 9
#pragma unroll 1
    for (int t = 0; t < NT; ++t) {
        int buf = t & 1;
        if (t + 1 < NT) { OUT_LOAD(buf ^ 1, t + 1); CP_COMMIT(); CP_WAIT1(); }
        else           { CP_WAIT0(); }
        __syncthreads();
        uint32_t bb = base + (uint32_t)buf * bufB;
        int m0w = w * 16;
        MMA3_STEP(bb, bb + oAl, bb + oBh, bb + oBl, m0w);
        __syncthreads();
    }

    int gid = lane >> 2, tig = lane & 3;
    int r1 = n0 + w * 16 + gid;
    int r2 = r1 + 8;
    float dv1 = g_dinv[(size_t)bh * Nn + r1];
    float dv2 = g_dinv[(size_t)bh * Nn + r2];
    int b = bh >> 3, h = bh & 7;
    size_t b1 = (size_t)(b * Nn + r1) * K2 + h * 64;
    size_t b2 = (size_t)(b * Nn + r2) * K2 + h * 64;
#pragma unroll
    for (int nt = 0; nt < 8; nt++) {
        int c = nt * 8 + tig * 2;
        float v0 = acc[nt][0] * dv1, v1 = acc[nt][1] * dv1;
        float v2 = acc[nt][2] * dv2, v3 = acc[nt][3] * dv2;
        __nv_bfloat162 H1, L1, H2, L2;
        split2(v0, H1.x, L1.x); split2(v1, H1.y, L1.y);
        split2(v2, H2.x, L2.x); split2(v3, H2.y, L2.y);
        *(__nv_bfloat162*)(g_attn2 + b1 + c)        = H1;
        *(__nv_bfloat162*)(g_attn2 + b1 + 512 + c)  = L1;
        *(__nv_bfloat162*)(g_attn2 + b1 + 1024 + c) = H1;
        *(__nv_bfloat162*)(g_attn2 + b2 + c)        = H2;
        *(__nv_bfloat162*)(g_attn2 + b2 + 512 + c)  = L2;
        *(__nv_bfloat162*)(g_attn2 + b2 + 1024 + c) = H2;
    }
}

// -------------------- launch --------------------
extern "C" void kernel_launch(void* const* d_in, const int* in_sizes, int n_in,
                              void* d_out, int out_size) {
    const float* x    = (const float*)d_in[0];
    const float* Wq   = (const float*)d_in[1];
    const float* Wk   = (const float*)d_in[2];
    const float* Wv   = (const float*)d_in[3];
    const float* Wo   = (const float*)d_in[4];
    const float* bo   = (const float*)d_in[5];
    const float* proj = (const float*)d_in[6];
    float* out = (float*)d_out;
    (void)in_sizes; (void)n_in; (void)out_size;

    cudaFuncSetAttribute(k_ctx_t, cudaFuncAttributeMaxDynamicSharedMemorySize,
                         CTX_BUFE * 2 * 2);
    cudaFuncSetAttribute(k_out_t, cudaFuncAttributeMaxDynamicSharedMemorySize,
                         OUT_BUFE * 2 * 2);

    __nv_bfloat16 *x2p, *wq2p, *wk2p, *wv2p, *wo2p, *attn2p;
    cudaGetSymbolAddress((void**)&x2p, g_x2);
    cudaGetSymbolAddress((void**)&wq2p, g_wq2);
    cudaGetSymbolAddress((void**)&wk2p, g_wk2);
    cudaGetSymbolAddress((void**)&wv2p, g_wv2);
    cudaGetSymbolAddress((void**)&wo2p, g_wo2);
    cudaGetSymbolAddress((void**)&attn2p, g_attn2);
    float *qp_, *kp_, *vp_;
    cudaGetSymbolAddress((void**)&qp_, g_q);
    cudaGetSymbolAddress((void**)&kp_, g_k);
    cudaGetSymbolAddress((void**)&vp_, g_v);

    // launches 1-5: init + 4 splits, so launch #6 (ncu -s 5 -c 1) = big k_gemm
    k_init<<<(BHh * MX * DHd + 255) / 256, 256>>>();
    k_split<<<(BNn * 128 + 255) / 256, 256>>>(x, x2p, BNn, 512, 1024);
    k_split<<<(Dd * 128 + 255) / 256, 256>>>(Wq, wq2p, Dd, 1024, 512);
    k_split<<<(Dd * 128 + 255) / 256, 256>>>(Wk, wk2p, Dd, 1024, 512);
    k_split<<<(Dd * 128 + 255) / 256, 256>>>(Wv, wv2p, Dd, 1024, 512);

    dim3 gG(BNn / 128, Dd / 128);
    k_gemm<<<gG, 256>>>(x2p, wq2p, qp_, nullptr, nullptr, 0);   // launch #6: ncu target
    k_gemm<<<gG, 256>>>(x2p, wk2p, kp_, nullptr, nullptr, 0);
    k_gemm<<<gG, 256>>>(x2p, wv2p, vp_, nullptr, nullptr, 0);

    k_split<<<(Dd * 128 + 255) / 256, 256>>>(Wo, wo2p, Dd, 1024, 512);
    k_projB<<<(384 * 64 + 255) / 256, 256>>>(proj);

    k_prep<<<(int)(NROWS * 8 / 256), 256>>>(0);
    k_prep<<<(int)(NROWS * 8 / 256), 256>>>(1);
    k_phi<<<dim3((int)(NROWS / 128), 3), 256>>>(1);
    k_phi<<<dim3((int)(NROWS / 128), 3), 256>>>(0);
    k_exp_k<<<dim3(Nn / 64, BHh), 256>>>();
    k_exp_q<<<dim3(Nn / 64, BHh), 256>>>();
    k_vt<<<dim3(Nn / 64, BHh), 256>>>();

    k_ctx_t<<<dim3(3, 8, BHh), 192, CTX_BUFE * 2 * 2>>>();
    k_ctxT<<<BHh, 256>>>();
    k_out_t<<<dim3(Nn / 128, BHh), 256, OUT_BUFE * 2 * 2>>>();

    k_gemm<<<gG, 256>>>(attn2p, wo2p, out, x, bo, 1);
}

// round 9
// speedup vs baseline: 1.3362x; 1.3362x over previous
#include <cuda_runtime.h>
#include <cuda_bf16.h>
#include <stdint.h>
#include <math.h>

#define Bb   4
#define Nn   4096
#define Dd   512
#define Hh   8
#define DHd  64
#define Mm   266
#define BHh  32          // B*H
#define BNn  16384       // B*N
#define MPAD 268
#define K2   1536        // split-bf16 expanded K (hi|lo|hi)

// -------------------- scratch (static device memory; no allocs) --------------------
__device__ float g_q  [(size_t)BHh * Nn * DHd];
__device__ float g_k  [(size_t)BHh * Nn * DHd];
__device__ float g_v  [(size_t)BHh * Nn * DHd];
__device__ float g_qp [(size_t)BHh * Nn * Mm];
__device__ float g_kp [(size_t)BHh * Nn * Mm];
__device__ float g_ctx [(size_t)BHh * Mm * DHd];
__device__ float g_ksum[(size_t)BHh * Mm];
__device__ float g_kmax[BHh];
__device__ float g_diag[(size_t)BHh * Nn];
__device__ float g_dinv[(size_t)BHh * Nn];

__device__ __nv_bfloat16 g_x2   [(size_t)BNn * K2];
__device__ __nv_bfloat16 g_attn2[(size_t)BNn * K2];
__device__ __nv_bfloat16 g_wq2  [(size_t)Dd * K2];
__device__ __nv_bfloat16 g_wk2  [(size_t)Dd * K2];
__device__ __nv_bfloat16 g_wv2  [(size_t)Dd * K2];
__device__ __nv_bfloat16 g_wo2  [(size_t)Dd * K2];

// -------------------- helpers --------------------
typedef unsigned long long u64t;

__device__ __forceinline__ uint32_t smem_to_u32(const void* p) {
    uint32_t a;
    asm("{ .reg .u64 t; cvta.to.shared.u64 t, %1; cvt.u32.u64 %0, t; }"
        : "=r"(a) : "l"(p));
    return a;
}

#define CP_ASYNC16(dst, src) \
    asm volatile("cp.async.cg.shared.global [%0], [%1], 16;" \
                 :: "r"(dst), "l"(src) : "memory")
#define CP_COMMIT()  asm volatile("cp.async.commit_group;" ::: "memory")
#define CP_WAIT1()   asm volatile("cp.async.wait_group 1;" ::: "memory")
#define CP_WAIT0()   asm volatile("cp.async.wait_group 0;" ::: "memory")

__device__ __forceinline__ void ldm_x4(uint32_t& r0, uint32_t& r1,
                                       uint32_t& r2, uint32_t& r3, uint32_t addr) {
    asm volatile("ldmatrix.sync.aligned.m8n8.x4.shared.b16 {%0,%1,%2,%3}, [%4];"
                 : "=r"(r0), "=r"(r1), "=r"(r2), "=r"(r3) : "r"(addr));
}

__device__ __forceinline__ void mma16816(float* c, const uint32_t* a, const uint32_t* b) {
    asm volatile(
        "mma.sync.aligned.m16n8k16.row.col.f32.bf16.bf16.f32 "
        "{%0,%1,%2,%3}, {%4,%5,%6,%7}, {%8,%9}, {%0,%1,%2,%3};"
        : "+f"(c[0]), "+f"(c[1]), "+f"(c[2]), "+f"(c[3])
        : "r"(a[0]), "r"(a[1]), "r"(a[2]), "r"(a[3]), "r"(b[0]), "r"(b[1]));
}

// ---- packed fp32x2 FMA (Blackwell base ISA) ----
__device__ __forceinline__ u64t pack2(float x, float y) {
    u64t r;
    asm("mov.b64 %0, {%1, %2};" : "=l"(r) : "f"(x), "f"(y));
    return r;
}
__device__ __forceinline__ u64t bcast2(float v) {
    u64t r;
    asm("mov.b64 %0, {%1, %1};" : "=l"(r) : "f"(v));
    return r;
}
__device__ __forceinline__ void ffma2(u64t& c, u64t a, u64t b) {
    asm("fma.rn.f32x2 %0, %1, %2, %0;" : "+l"(c) : "l"(a), "l"(b));
}
__device__ __forceinline__ float lane0(u64t v) { float2 t; *(u64t*)&t = v; return t.x; }
__device__ __forceinline__ float lane1(u64t v) { float2 t; *(u64t*)&t = v; return t.y; }
#define ACC2F(i, j) (((i) & 1) ? lane1(acc2[(i) >> 1][j]) : lane0(acc2[(i) >> 1][j]))

// 8x ffma2 micro-step shared by all tail kernels:
// rows (i) packed in pairs from float4 a; cols (j) broadcast from float4 b.
#define F32X2_STEP(a4, b4) do {                                   \
    u64t a01 = pack2((a4).x, (a4).y), a23 = pack2((a4).z, (a4).w);\
    u64t bb0 = bcast2((b4).x), bb1 = bcast2((b4).y);              \
    u64t bb2 = bcast2((b4).z), bb3 = bcast2((b4).w);              \
    ffma2(acc2[0][0], a01, bb0); ffma2(acc2[0][1], a01, bb1);     \
    ffma2(acc2[0][2], a01, bb2); ffma2(acc2[0][3], a01, bb3);     \
    ffma2(acc2[1][0], a23, bb0); ffma2(acc2[1][1], a23, bb1);     \
    ffma2(acc2[1][2], a23, bb2); ffma2(acc2[1][3], a23, bb3);     \
} while (0)

__device__ __forceinline__ void atomicMaxF(float* addr, float val) {
    int* ai = (int*)addr;
    int old = *ai;
    while (__int_as_float(old) < val) {
        int assumed = old;
        old = atomicCAS(ai, assumed, __float_as_int(val));
        if (old == assumed) break;
    }
}

__device__ __forceinline__ float fast_exp(float x) {
    float y = fmaxf(x * 1.4426950408889634f, -126.0f);
    float r = rintf(y);
    float f = y - r;
    float p = 1.5403530e-4f;
    p = fmaf(p, f, 1.3333558e-3f);
    p = fmaf(p, f, 9.6181291e-3f);
    p = fmaf(p, f, 5.5504109e-2f);
    p = fmaf(p, f, 2.4022651e-1f);
    p = fmaf(p, f, 6.9314718e-1f);
    p = fmaf(p, f, 1.0f);
    int e = (int)r;
    float s = __int_as_float((e + 127) << 23);
    return p * s;
}

#define NORMALIZER 0.35355339059327373f   // 64^-0.25
#define RATIO      0.061313934f           // 266^-0.5
#define EPSF       1e-4f

// -------------------- init scratch accumulators --------------------
__global__ void k_init() {
    int i = blockIdx.x * 256 + threadIdx.x;
    if (i < BHh * Mm * DHd) g_ctx[i]  = 0.0f;
    if (i < BHh * Mm)       g_ksum[i] = 0.0f;
    if (i < BHh)            g_kmax[i] = -3.0e38f;
}

// -------------------- fp32 -> split bf16 (hi|lo|hi at given offsets) --------------------
__global__ __launch_bounds__(256) void k_split(const float* __restrict__ src,
                                               __nv_bfloat16* __restrict__ dst,
                                               int nrows, int loOff, int dupOff) {
    int i = blockIdx.x * 256 + threadIdx.x;
    int total = nrows * 128;   // 4 floats per thread
    if (i >= total) return;
    int r = i >> 7;
    int c = (i & 127) << 2;
    float4 v = *(const float4*)(src + (size_t)r * 512 + c);
    __nv_bfloat16 h0 = __float2bfloat16(v.x), h1 = __float2bfloat16(v.y);
    __nv_bfloat16 h2 = __float2bfloat16(v.z), h3 = __float2bfloat16(v.w);
    __nv_bfloat16 l0 = __float2bfloat16(v.x - __bfloat162float(h0));
    __nv_bfloat16 l1 = __float2bfloat16(v.y - __bfloat162float(h1));
    __nv_bfloat16 l2 = __float2bfloat16(v.z - __bfloat162float(h2));
    __nv_bfloat16 l3 = __float2bfloat16(v.w - __bfloat162float(h3));
    size_t rb = (size_t)r * K2;
    __nv_bfloat162 H01; H01.x = h0; H01.y = h1;
    __nv_bfloat162 H23; H23.x = h2; H23.y = h3;
    __nv_bfloat162 L01; L01.x = l0; L01.y = l1;
    __nv_bfloat162 L23; L23.x = l2; L23.y = l3;
    *(__nv_bfloat162*)(dst + rb + c)              = H01;
    *(__nv_bfloat162*)(dst + rb + c + 2)          = H23;
    *(__nv_bfloat162*)(dst + rb + loOff + c)      = L01;
    *(__nv_bfloat162*)(dst + rb + loOff + c + 2)  = L23;
    *(__nv_bfloat162*)(dst + rb + dupOff + c)     = H01;
    *(__nv_bfloat162*)(dst + rb + dupOff + c + 2) = H23;
}

// -------------------- mma.sync GEMM: C[16384,512] = A2[16384,K2] @ B2[512,K2]^T --------
#define ASTR 40              // padded bf16 per smem row (80B, conflict-free ldmatrix)
#define TILE_B (128 * ASTR)  // bf16 elems per buffer

__global__ __launch_bounds__(256) void k_gemm(const __nv_bfloat16* __restrict__ A,
                                              const __nv_bfloat16* __restrict__ Bw,
                                              float* __restrict__ C,
                                              const float* __restrict__ xres,
                                              const float* __restrict__ bo,
                                              int finalmode) {
    __shared__ __nv_bfloat16 sA[2][TILE_B];
    __shared__ __nv_bfloat16 sB[2][TILE_B];
    int tid = threadIdx.x, lane = tid & 31, w = tid >> 5;
    int m0 = (w & 3) * 32, n0 = (w >> 2) * 64;
    int r0 = blockIdx.x * 128, e0 = blockIdx.y * 128;
    uint32_t sAu = smem_to_u32(sA), sBu = smem_to_u32(sB);

    float acc[2][8][4];
#pragma unroll
    for (int i = 0; i < 2; i++)
#pragma unroll
        for (int j = 0; j < 8; j++)
#pragma unroll
            for (int l = 0; l < 4; l++) acc[i][j][l] = 0.f;

    int lrow = tid >> 1;
    int lcol = (tid & 1) << 4;
    const __nv_bfloat16* Arow = A + (size_t)(r0 + lrow) * K2 + lcol;
    const __nv_bfloat16* Brow = Bw + (size_t)(e0 + lrow) * K2 + lcol;
    uint32_t sAdst = sAu + (uint32_t)(lrow * ASTR + lcol) * 2;
    uint32_t sBdst = sBu + (uint32_t)(lrow * ASTR + lcol) * 2;

#define LOAD_TILE(buf, t) do {                                         \
    uint32_t _o = (uint32_t)(buf) * (TILE_B * 2);                      \
    const __nv_bfloat16* _a = Arow + (t) * 32;                         \
    const __nv_bfloat16* _b = Brow + (t) * 32;                         \
    CP_ASYNC16(sAdst + _o,      _a);                                   \
    CP_ASYNC16(sAdst + _o + 16, _a + 8);                               \
    CP_ASYNC16(sBdst + _o,      _b);                                   \
    CP_ASYNC16(sBdst + _o + 16, _b + 8);                               \
} while (0)

    LOAD_TILE(0, 0);
    CP_COMMIT();

    const int NT = K2 / 32;   // 48
#pragma unroll 1
    for (int t = 0; t < NT; ++t) {
        int buf = t & 1;
        if (t + 1 < NT) {
            LOAD_TILE(buf ^ 1, t + 1);
            CP_COMMIT();
            CP_WAIT1();
        } else {
            CP_WAIT0();
        }
        __syncthreads();

        uint32_t ab = sAu + (uint32_t)buf * (TILE_B * 2);
        uint32_t bb = sBu + (uint32_t)buf * (TILE_B * 2);
#pragma unroll
        for (int ks = 0; ks < 32; ks += 16) {
            uint32_t a[2][4];
#pragma unroll
            for (int mt = 0; mt < 2; mt++) {
                uint32_t addr = ab +
                    (uint32_t)((m0 + mt * 16 + (lane & 15)) * ASTR + ks + ((lane >> 4) << 3)) * 2;
                ldm_x4(a[mt][0], a[mt][1], a[mt][2], a[mt][3], addr);
            }
            uint32_t b[8][2];
#pragma unroll
            for (int p = 0; p < 4; p++) {
                int nA = n0 + p * 16;
                uint32_t addr = bb +
                    (uint32_t)((nA + (lane & 7) + ((lane >> 4) << 3)) * ASTR + ks + (lane & 8)) * 2;
                ldm_x4(b[2 * p][0], b[2 * p][1], b[2 * p + 1][0], b[2 * p + 1][1], addr);
            }
#pragma unroll
            for (int mt = 0; mt < 2; mt++)
#pragma unroll
                for (int nt = 0; nt < 8; nt++)
                    mma16816(acc[mt][nt], a[mt], b[nt]);
        }
        __syncthreads();
    }

    int gid = lane >> 2, tig = lane & 3;
#pragma unroll
    for (int mt = 0; mt < 2; mt++) {
#pragma unroll
        for (int nt = 0; nt < 8; nt++) {
            int r = r0 + m0 + mt * 16 + gid;
            int e = e0 + n0 + nt * 8 + tig * 2;
            float2 v01 = make_float2(acc[mt][nt][0], acc[mt][nt][1]);
            float2 v23 = make_float2(acc[mt][nt][2], acc[mt][nt][3]);
            if (!finalmode) {
                int b = r >> 12, n = r & 4095;
                int h = e >> 6, dh = e & 63;
                float* d0 = C + (((size_t)((b << 3) + h) * Nn + n) * DHd + dh);
                *(float2*)d0 = v01;
                *(float2*)(d0 + 8 * DHd) = v23;
            } else {
                size_t b0 = (size_t)r * Dd + e;
                float2 x0 = *(const float2*)(xres + b0);
                float2 x1 = *(const float2*)(xres + b0 + 8 * Dd);
                float2 bv = *(const float2*)(bo + e);
                *(float2*)(C + b0) = make_float2(x0.x + bv.x + v01.x, x0.y + bv.y + v01.y);
                *(float2*)(C + b0 + 8 * Dd) = make_float2(x1.x + bv.x + v23.x, x1.y + bv.y + v23.y);
            }
        }
    }
}

// -------------------- phi_k pass 1: td = (k*nrm)@proj^T, diag, per-head max --------------------
__global__ __launch_bounds__(256) void k_phi_k(const float* __restrict__ proj) {
    __shared__ float Ks[64][68];   // [dh][n]
    __shared__ float Ps[64][68];   // [dh][m]
    __shared__ float red[256];
    int tid = threadIdx.x;
    int n0 = blockIdx.x * 64;
    int m0 = blockIdx.y * 64;
    int bh = blockIdx.z;

#pragma unroll
    for (int i = 0; i < 4; i++) {
        int s = tid + i * 256;
        int row = s >> 4;
        int kc = (s & 15) << 2;
        float4 a = *(const float4*)(g_k + ((size_t)bh * Nn + n0 + row) * DHd + kc);
        Ks[kc + 0][row] = a.x * NORMALIZER; Ks[kc + 1][row] = a.y * NORMALIZER;
        Ks[kc + 2][row] = a.z * NORMALIZER; Ks[kc + 3][row] = a.w * NORMALIZER;
        float4 p = make_float4(0.f, 0.f, 0.f, 0.f);
        if (m0 + row < Mm) p = *(const float4*)(proj + (size_t)(m0 + row) * DHd + kc);
        Ps[kc + 0][row] = p.x; Ps[kc + 1][row] = p.y;
        Ps[kc + 2][row] = p.z; Ps[kc + 3][row] = p.w;
    }
    __syncthreads();

    if (m0 == 0 && tid < 64) {
        float ss = 0.f;
#pragma unroll
        for (int d = 0; d < 64; d++) { float q = Ks[d][tid]; ss += q * q; }
        g_diag[(size_t)bh * Nn + n0 + tid] = 0.5f * ss;
    }

    u64t acc2[2][4];
#pragma unroll
    for (int i = 0; i < 2; i++)
#pragma unroll
        for (int j = 0; j < 4; j++) acc2[i][j] = 0ull;
    int ty = tid >> 4, tx = tid & 15;
#pragma unroll
    for (int kk = 0; kk < 64; kk++) {
        float4 a = *(const float4*)&Ks[kk][ty * 4];
        float4 b = *(const float4*)&Ps[kk][tx * 4];
        F32X2_STEP(a, b);
    }

    float mymax = -3.0e38f;
#pragma unroll
    for (int i = 0; i < 4; i++) {
        int n = n0 + ty * 4 + i;
#pragma unroll
        for (int j = 0; j < 4; j++) {
            int m = m0 + tx * 4 + j;
            if (m < Mm) {
                float av = ACC2F(i, j);
                g_kp[((size_t)bh * Nn + n) * Mm + m] = av;
                mymax = fmaxf(mymax, av);
            }
        }
    }
    red[tid] = mymax;
    __syncthreads();
    for (int off = 128; off > 0; off >>= 1) {
        if (tid < off) red[tid] = fmaxf(red[tid], red[tid + off]);
        __syncthreads();
    }
    if (tid == 0) atomicMaxF(&g_kmax[bh], red[0]);
}

// -------------------- phi_k pass 2: exp + column sums --------------------
__global__ __launch_bounds__(256) void k_exp_k() {
    __shared__ float diag_s[64];
    int tid = threadIdx.x;
    int n0 = blockIdx.x * 64;
    int bh = blockIdx.y;
    if (tid < 64) diag_s[tid] = g_diag[(size_t)bh * Nn + n0 + tid];
    __syncthreads();
    float mx = g_kmax[bh];
    for (int m = tid; m < Mm; m += 256) {
        size_t base = ((size_t)bh * Nn + n0) * Mm + m;
        float cs = 0.f;
#pragma unroll 4
        for (int r = 0; r < 64; r++) {
            float td = g_kp[base + (size_t)r * Mm];
            float v = RATIO * (fast_exp(td - diag_s[r] - mx) + EPSF);
            g_kp[base + (size_t)r * Mm] = v;
            cs += v;
        }
        atomicAdd(&g_ksum[bh * Mm + m], cs);
    }
}

// -------------------- phi_q fully fused: td -> rowmax -> exp -> qp + d_inv --------------------
#define QP_SMEM_FLOATS (4352 + 4352 + 17152 + MPAD + 64)
__global__ __launch_bounds__(256) void k_phi_q(const float* __restrict__ proj) {
    extern __shared__ float sm[];
    float* Qs     = sm;                       // 64*68  [dh][n]
    float* Ps     = sm + 4352;                // 64*68  [dh][m]
    float* tds    = sm + 8704;                // 64*MPAD
    float* ksum_s = sm + 8704 + 17152;        // MPAD
    float* diag_s = ksum_s + MPAD;            // 64

    int tid = threadIdx.x;
    int n0 = blockIdx.x * 64;
    int bh = blockIdx.y;

    for (int i = tid; i < Mm; i += 256) ksum_s[i] = g_ksum[bh * Mm + i];

#pragma unroll
    for (int i = 0; i < 4; i++) {
        int s = tid + i * 256;
        int row = s >> 4;
        int kc = (s & 15) << 2;
        float4 a = *(const float4*)(g_q + ((size_t)bh * Nn + n0 + row) * DHd + kc);
        Qs[(kc + 0) * 68 + row] = a.x * NORMALIZER;
        Qs[(kc + 1) * 68 + row] = a.y * NORMALIZER;
        Qs[(kc + 2) * 68 + row] = a.z * NORMALIZER;
        Qs[(kc + 3) * 68 + row] = a.w * NORMALIZER;
    }
    __syncthreads();
    if (tid < 64) {
        float ss = 0.f;
#pragma unroll
        for (int d = 0; d < 64; d++) { float q = Qs[d * 68 + tid]; ss += q * q; }
        diag_s[tid] = 0.5f * ss;
    }

    int ty = tid >> 4, tx = tid & 15;
    for (int mt = 0; mt < 5; mt++) {
        int m0 = mt * 64;
#pragma unroll
        for (int i = 0; i < 4; i++) {
            int s = tid + i * 256;
            int row = s >> 4;
            int kc = (s & 15) << 2;
            float4 p = make_float4(0.f, 0.f, 0.f, 0.f);
            if (m0 + row < Mm) p = *(const float4*)(proj + (size_t)(m0 + row) * DHd + kc);
            Ps[(kc + 0) * 68 + row] = p.x;
            Ps[(kc + 1) * 68 + row] = p.y;
            Ps[(kc + 2) * 68 + row] = p.z;
            Ps[(kc + 3) * 68 + row] = p.w;
        }
        __syncthreads();
        u64t acc2[2][4];
#pragma unroll
        for (int i = 0; i < 2; i++)
#pragma unroll
            for (int j = 0; j < 4; j++) acc2[i][j] = 0ull;
#pragma unroll
        for (int kk = 0; kk < 64; kk++) {
            float4 a = *(const float4*)&Qs[kk * 68 + ty * 4];
            float4 b = *(const float4*)&Ps[kk * 68 + tx * 4];
            F32X2_STEP(a, b);
        }
#pragma unroll
        for (int i = 0; i < 4; i++)
#pragma unroll
            for (int j = 0; j < 4; j++) {
                int m = m0 + tx * 4 + j;
                if (m < Mm) tds[(ty * 4 + i) * MPAD + m] = ACC2F(i, j);
            }
        __syncthreads();
    }

    int row = tid >> 2, lane = tid & 3;
    float pm = -3.0e38f;
    for (int m = lane; m < Mm; m += 4) pm = fmaxf(pm, tds[row * MPAD + m]);
    pm = fmaxf(pm, __shfl_xor_sync(0xffffffffu, pm, 1));
    pm = fmaxf(pm, __shfl_xor_sync(0xffffffffu, pm, 2));
    float dg = diag_s[row];
    float sum = 0.f;
    size_t gb = ((size_t)bh * Nn + n0 + row) * Mm;
    for (int m = lane; m < Mm; m += 4) {
        float v = RATIO * (fast_exp(tds[row * MPAD + m] - dg - pm) + EPSF);
        g_qp[gb + m] = v;
        sum += v * ksum_s[m];
    }
    sum += __shfl_xor_sync(0xffffffffu, sum, 1);
    sum += __shfl_xor_sync(0xffffffffu, sum, 2);
    if (lane == 0) g_dinv[(size_t)bh * Nn + n0 + row] = 1.0f / sum;
}

// -------------------- context: ctx[m,dh] += sum_n kp[n,m]*v[n,dh] (split-K over n) --------------------
__global__ __launch_bounds__(256) void k_ctx() {
    __shared__ float Ksm[64][68];  // [n][m]
    __shared__ float Vs[64][68];   // [n][dh]
    int tid = threadIdx.x;
    int m0 = blockIdx.x * 64;
    int nc = blockIdx.y * 512;
    int bh = blockIdx.z;
    u64t acc2[2][4];
#pragma unroll
    for (int i = 0; i < 2; i++)
#pragma unroll
        for (int j = 0; j < 4; j++) acc2[i][j] = 0ull;
    int ty = tid >> 4, tx = tid & 15;

    for (int n0 = nc; n0 < nc + 512; n0 += 64) {
#pragma unroll
        for (int i = 0; i < 16; i++) {
            int s = tid + i * 256;
            int n = s >> 6, mm = s & 63;
            Ksm[n][mm] = (m0 + mm < Mm)
                             ? g_kp[((size_t)bh * Nn + n0 + n) * Mm + m0 + mm]
                             : 0.f;
        }
#pragma unroll
        for (int i = 0; i < 4; i++) {
            int s = tid + i * 256;
            int n = s >> 4, c = (s & 15) << 2;
            float4 v = *(const float4*)(g_v + ((size_t)bh * Nn + n0 + n) * DHd + c);
            Vs[n][c] = v.x; Vs[n][c + 1] = v.y; Vs[n][c + 2] = v.z; Vs[n][c + 3] = v.w;
        }
        __syncthreads();
#pragma unroll
        for (int kk = 0; kk < 64; kk++) {
            float4 a = *(const float4*)&Ksm[kk][ty * 4];
            float4 b = *(const float4*)&Vs[kk][tx * 4];
            F32X2_STEP(a, b);
        }
        __syncthreads();
    }
#pragma unroll
    for (int i = 0; i < 4; i++) {
        int m = m0 + ty * 4 + i;
        if (m < Mm)
#pragma unroll
            for (int j = 0; j < 4; j++)
                atomicAdd(&g_ctx[((size_t)bh * Mm + m) * DHd + tx * 4 + j], ACC2F(i, j));
    }
}

// -------------------- out: attn2 (split bf16) = d_inv[n] * sum_m qp[n,m]*ctx[m,dh] --------------------
__global__ __launch_bounds__(256) void k_out() {
    __shared__ float Qs[64][68];  // [k][n]
    __shared__ float Cs[64][68];  // [k][dh]
    int tid = threadIdx.x;
    int n0 = blockIdx.x * 64;
    int bh = blockIdx.y;
    u64t acc2[2][4];
#pragma unroll
    for (int i = 0; i < 2; i++)
#pragma unroll
        for (int j = 0; j < 4; j++) acc2[i][j] = 0ull;
    int ty = tid >> 4, tx = tid & 15;

    for (int c0 = 0; c0 < Mm; c0 += 64) {
#pragma unroll
        for (int i = 0; i < 16; i++) {
            int s = tid + i * 256;
            int r = s >> 6, kc = s & 63;
            Qs[kc][r] = (c0 + kc < Mm)
                            ? g_qp[((size_t)bh * Nn + n0 + r) * Mm + c0 + kc]
                            : 0.f;
        }
#pragma unroll
        for (int i = 0; i < 16; i++) {
            int s = tid + i * 256;
            int kk = s >> 6, dh = s & 63;
            Cs[kk][dh] = (c0 + kk < Mm)
                             ? g_ctx[((size_t)bh * Mm + c0 + kk) * DHd + dh]
                             : 0.f;
        }
        __syncthreads();
#pragma unroll
        for (int kk = 0; kk < 64; kk++) {
            float4 a = *(const float4*)&Qs[kk][ty * 4];
            float4 b = *(const float4*)&Cs[kk][tx * 4];
            F32X2_STEP(a, b);
        }
        __syncthreads();
    }
    int b = bh >> 3, h = bh & 7;
#pragma unroll
    for (int i = 0; i < 4; i++) {
        int n = n0 + ty * 4 + i;
        float dv = g_dinv[(size_t)bh * Nn + n];
        size_t rb = (size_t)(b * Nn + n) * K2 + h * 64 + tx * 4;
#pragma unroll
        for (int j = 0; j < 4; j++) {
            float val = ACC2F(i, j) * dv;
            __nv_bfloat16 hv = __float2bfloat16(val);
            __nv_bfloat16 lv = __float2bfloat16(val - __bfloat162float(hv));
            g_attn2[rb + j]        = hv;   // hi
            g_attn2[rb + 512 + j]  = lv;   // lo  (pairs with Wo hi)
            g_attn2[rb + 1024 + j] = hv;   // hi  (pairs with Wo lo)
        }
    }
}

// -------------------- launch --------------------
extern "C" void kernel_launch(void* const* d_in, const int* in_sizes, int n_in,
                              void* d_out, int out_size) {
    const float* x    = (const float*)d_in[0];
    const float* Wq   = (const float*)d_in[1];
    const float* Wk   = (const float*)d_in[2];
    const float* Wv   = (const float*)d_in[3];
    const float* Wo   = (const float*)d_in[4];
    const float* bo   = (const float*)d_in[5];
    const float* proj = (const float*)d_in[6];
    float* out = (float*)d_out;
    (void)in_sizes; (void)n_in; (void)out_size;

    cudaFuncSetAttribute(k_phi_q, cudaFuncAttributeMaxDynamicSharedMemorySize,
                         QP_SMEM_FLOATS * (int)sizeof(float));

    __nv_bfloat16 *x2p, *wq2p, *wk2p, *wv2p, *wo2p, *attn2p;
    cudaGetSymbolAddress((void**)&x2p, g_x2);
    cudaGetSymbolAddress((void**)&wq2p, g_wq2);
    cudaGetSymbolAddress((void**)&wk2p, g_wk2);
    cudaGetSymbolAddress((void**)&wv2p, g_wv2);
    cudaGetSymbolAddress((void**)&wo2p, g_wo2);
    cudaGetSymbolAddress((void**)&attn2p, g_attn2);
    float *qp_, *kp_, *vp_;
    cudaGetSymbolAddress((void**)&qp_, g_q);
    cudaGetSymbolAddress((void**)&kp_, g_k);
    cudaGetSymbolAddress((void**)&vp_, g_v);

    // launches 1-5: init + 4 splits, so launch #6 (ncu -s 5 -c 1) = big k_gemm
    k_init<<<(BHh * Mm * DHd + 255) / 256, 256>>>();
    k_split<<<(BNn * 128 + 255) / 256, 256>>>(x, x2p, BNn, 512, 1024);
    k_split<<<(Dd * 128 + 255) / 256, 256>>>(Wq, wq2p, Dd, 1024, 512);
    k_split<<<(Dd * 128 + 255) / 256, 256>>>(Wk, wk2p, Dd, 1024, 512);
    k_split<<<(Dd * 128 + 255) / 256, 256>>>(Wv, wv2p, Dd, 1024, 512);

    dim3 gG(BNn / 128, Dd / 128);
    k_gemm<<<gG, 256>>>(x2p, wq2p, qp_, nullptr, nullptr, 0);   // launch #6: ncu target
    k_gemm<<<gG, 256>>>(x2p, wk2p, kp_, nullptr, nullptr, 0);
    k_gemm<<<gG, 256>>>(x2p, wv2p, vp_, nullptr, nullptr, 0);

    k_split<<<(Dd * 128 + 255) / 256, 256>>>(Wo, wo2p, Dd, 1024, 512);

    k_phi_k<<<dim3(Nn / 64, 5, BHh), 256>>>(proj);
    k_exp_k<<<dim3(Nn / 64, BHh), 256>>>();
    k_phi_q<<<dim3(Nn / 64, BHh), 256, QP_SMEM_FLOATS * (int)sizeof(float)>>>(proj);

    k_ctx<<<dim3(5, Nn / 512, BHh), 256>>>();
    k_out<<<dim3(Nn / 64, BHh), 256>>>();

    k_gemm<<<gG, 256>>>(attn2p, wo2p, out, x, bo, 1);
}